// round 5
// baseline (speedup 1.0000x reference)
#include <cuda_runtime.h>

#define NN 100000
#define EE 1200000
#define NB 98            // ceil(NN / 1024)

// ---------------- scratch (device globals; no allocation allowed) ------------
__device__ __align__(16) int   g_degi[NN];
__device__ __align__(16) int   g_cnt [NN];
__device__ __align__(16) int   g_ptr [NN];        // CSR row start (exclusive scan)
__device__ __align__(16) int   g_bsum[NB];
__device__ __align__(16) int   g_boff[NB];
__device__ __align__(16) float g_dis [NN];
__device__ __align__(16) int   g_csr_col[EE];
__device__ __align__(16) float g_csr_w  [EE];
__device__ __align__(16) float g_H  [(size_t)NN * 64];  // layer1: C0 (+b1), then += P(B)
__device__ __align__(16) float g_B  [(size_t)NN * 64];  // layer1: C1, then += 2P(C2)
__device__ __align__(16) float g_C2 [(size_t)NN * 64];  // layer1: x@W1[2]
__device__ __align__(16) float g_B2 [(size_t)NN * 32];  // layer2: C1', then += 2P(C2')
__device__ __align__(16) float g_C22[(size_t)NN * 32];  // layer2: relu(H)@W2[2]

// ---------------- degree / CSR build -----------------------------------------
__global__ void k_init() {
    int i = blockIdx.x * blockDim.x + threadIdx.x;
    if (i < NN) { g_degi[i] = 0; g_cnt[i] = 0; }
}

__global__ void k_deg(const int* __restrict__ row) {
    int e = blockIdx.x * blockDim.x + threadIdx.x;
    if (e < EE) {
        int r = row[e];
        if (r >= 0 && r < NN) atomicAdd(&g_degi[r], 1);
    }
}

__global__ __launch_bounds__(1024) void k_scan1() {
    __shared__ int s[1024];
    int i = blockIdx.x * 1024 + threadIdx.x;
    int v = (i < NN) ? g_degi[i] : 0;
    s[threadIdx.x] = v;
    __syncthreads();
    for (int off = 1; off < 1024; off <<= 1) {
        int a = (threadIdx.x >= off) ? s[threadIdx.x - off] : 0;
        __syncthreads();
        s[threadIdx.x] += a;
        __syncthreads();
    }
    if (i < NN) g_ptr[i] = s[threadIdx.x] - v;      // exclusive scan within block
    if (threadIdx.x == 1023) g_bsum[blockIdx.x] = s[1023];
}

__global__ void k_scan2() {
    if (threadIdx.x == 0) {
        int acc = 0;
        for (int b = 0; b < NB; b++) { g_boff[b] = acc; acc += g_bsum[b]; }
    }
}

__global__ void k_scan3() {
    int i = blockIdx.x * blockDim.x + threadIdx.x;
    if (i < NN) g_ptr[i] += g_boff[i >> 10];
}

__global__ void k_dis() {
    int i = blockIdx.x * blockDim.x + threadIdx.x;
    if (i < NN) {
        int d = g_degi[i];
        g_dis[i] = (d > 0) ? rsqrtf((float)d) : 0.f;
    }
}

__global__ void k_fill(const int* __restrict__ row, const int* __restrict__ col) {
    int e = blockIdx.x * blockDim.x + threadIdx.x;
    if (e < EE) {
        int r = row[e];
        int c = col[e];
        if (r < 0 || r >= NN || c < 0 || c >= NN) return;
        int slot = g_ptr[r] + atomicAdd(&g_cnt[r], 1);
        g_csr_col[slot] = c;
        g_csr_w[slot]   = g_dis[r] * g_dis[c];
    }
}

// ---------------- fused GEMM, layer 1: x[N,64] -> {H=C0+b1, B=C1, C2} --------
// blockIdx.y: 0 -> g_H (W1[0]-W1[2], +b1), 1 -> g_B (W1[1]), 2 -> g_C2 (W1[2])
__global__ __launch_bounds__(256) void k_gemm1(const float* __restrict__ x,
                                               const float* __restrict__ W1,
                                               const float* __restrict__ b1) {
    __shared__ float sX[64][68];   // transposed: [channel][node], padded
    __shared__ float sW[64][64];   // [channel][outcol]
    const int n0    = blockIdx.x * 64;
    const int which = blockIdx.y;
    const int tid   = threadIdx.x;

    for (int i = tid; i < 1024; i += 256) {
        int n = i >> 4, c4 = i & 15;
        float4 v = make_float4(0.f, 0.f, 0.f, 0.f);
        if (n0 + n < NN)
            v = reinterpret_cast<const float4*>(x)[(size_t)(n0 + n) * 16 + c4];
        sX[c4 * 4 + 0][n] = v.x; sX[c4 * 4 + 1][n] = v.y;
        sX[c4 * 4 + 2][n] = v.z; sX[c4 * 4 + 3][n] = v.w;
    }
    for (int i = tid; i < 1024; i += 256) {
        int c = i >> 4, o4 = i & 15;
        float4 w = reinterpret_cast<const float4*>(W1 + which * 4096)[c * 16 + o4];
        if (which == 0) {
            float4 w2 = reinterpret_cast<const float4*>(W1 + 2 * 4096)[c * 16 + o4];
            w.x -= w2.x; w.y -= w2.y; w.z -= w2.z; w.w -= w2.w;
        }
        reinterpret_cast<float4*>(&sW[c][0])[o4] = w;
    }
    __syncthreads();

    const int tx = tid & 15;
    const int ty = tid >> 4;
    float acc[4][4];
#pragma unroll
    for (int i = 0; i < 4; i++)
#pragma unroll
        for (int j = 0; j < 4; j++) acc[i][j] = 0.f;

#pragma unroll 16
    for (int k = 0; k < 64; ++k) {
        float4 a = *reinterpret_cast<const float4*>(&sX[k][ty * 4]);
        float4 w = *reinterpret_cast<const float4*>(&sW[k][tx * 4]);
        float av[4] = {a.x, a.y, a.z, a.w};
        float wv[4] = {w.x, w.y, w.z, w.w};
#pragma unroll
        for (int i = 0; i < 4; i++)
#pragma unroll
            for (int j = 0; j < 4; j++) acc[i][j] += av[i] * wv[j];
    }

    float4 bv = make_float4(0.f, 0.f, 0.f, 0.f);
    if (which == 0) bv = reinterpret_cast<const float4*>(b1)[tx];
    float* dst = (which == 0) ? g_H : (which == 1) ? g_B : g_C2;
#pragma unroll
    for (int i = 0; i < 4; i++) {
        int n = n0 + ty * 4 + i;
        if (n < NN) {
            float4 r = make_float4(acc[i][0] + bv.x, acc[i][1] + bv.y,
                                   acc[i][2] + bv.z, acc[i][3] + bv.w);
            reinterpret_cast<float4*>(dst)[(size_t)n * 16 + tx] = r;
        }
    }
}

// ---------------- fused GEMM, layer 2: relu(H)[N,64] -> {out=C0'+b2, B2, C22}
__global__ __launch_bounds__(128) void k_gemm2(float* __restrict__ out,
                                               const float* __restrict__ W2,
                                               const float* __restrict__ b2) {
    __shared__ float sX[64][68];
    __shared__ float sW[64][32];
    const int n0    = blockIdx.x * 64;
    const int which = blockIdx.y;
    const int tid   = threadIdx.x;

    for (int i = tid; i < 1024; i += 128) {
        int n = i >> 4, c4 = i & 15;
        float4 v = make_float4(0.f, 0.f, 0.f, 0.f);
        if (n0 + n < NN) {
            v = reinterpret_cast<const float4*>(g_H)[(size_t)(n0 + n) * 16 + c4];
            v.x = fmaxf(v.x, 0.f); v.y = fmaxf(v.y, 0.f);
            v.z = fmaxf(v.z, 0.f); v.w = fmaxf(v.w, 0.f);
        }
        sX[c4 * 4 + 0][n] = v.x; sX[c4 * 4 + 1][n] = v.y;
        sX[c4 * 4 + 2][n] = v.z; sX[c4 * 4 + 3][n] = v.w;
    }
    for (int i = tid; i < 512; i += 128) {
        int c = i >> 3, o4 = i & 7;
        float4 w = reinterpret_cast<const float4*>(W2 + which * 2048)[c * 8 + o4];
        if (which == 0) {
            float4 w2 = reinterpret_cast<const float4*>(W2 + 2 * 2048)[c * 8 + o4];
            w.x -= w2.x; w.y -= w2.y; w.z -= w2.z; w.w -= w2.w;
        }
        reinterpret_cast<float4*>(&sW[c][0])[o4] = w;
    }
    __syncthreads();

    const int tx = tid & 7;
    const int ty = tid >> 3;
    float acc[4][4];
#pragma unroll
    for (int i = 0; i < 4; i++)
#pragma unroll
        for (int j = 0; j < 4; j++) acc[i][j] = 0.f;

#pragma unroll 16
    for (int k = 0; k < 64; ++k) {
        float4 a = *reinterpret_cast<const float4*>(&sX[k][ty * 4]);
        float4 w = *reinterpret_cast<const float4*>(&sW[k][tx * 4]);
        float av[4] = {a.x, a.y, a.z, a.w};
        float wv[4] = {w.x, w.y, w.z, w.w};
#pragma unroll
        for (int i = 0; i < 4; i++)
#pragma unroll
            for (int j = 0; j < 4; j++) acc[i][j] += av[i] * wv[j];
    }

    float4 bv = make_float4(0.f, 0.f, 0.f, 0.f);
    if (which == 0) bv = reinterpret_cast<const float4*>(b2)[tx];
    float* dst = (which == 0) ? out : (which == 1) ? g_B2 : g_C22;
#pragma unroll
    for (int i = 0; i < 4; i++) {
        int n = n0 + ty * 4 + i;
        if (n < NN) {
            float4 r = make_float4(acc[i][0] + bv.x, acc[i][1] + bv.y,
                                   acc[i][2] + bv.z, acc[i][3] + bv.w);
            reinterpret_cast<float4*>(dst)[(size_t)n * 8 + tx] = r;
        }
    }
}

// ---------------- pull-style propagation: dst[r] += scale * sum_e w*src[col] -
// G = channels/4 (16 for 64ch, 8 for 32ch). One G-thread group per row.
// No atomics: each group exclusively owns its destination row.
template <int G, int MODE>
__global__ __launch_bounds__(256) void k_prop(float* __restrict__ dout, float scale) {
    unsigned t = blockIdx.x * 256u + threadIdx.x;
    unsigned r = t / G;
    unsigned g = t & (G - 1);
    if (r >= NN) return;

    const float* src;
    float* dst;
    if (MODE == 0)      { src = g_C2;  dst = g_B;  }
    else if (MODE == 1) { src = g_B;   dst = g_H;  }
    else if (MODE == 2) { src = g_C22; dst = g_B2; }
    else                { src = g_B2;  dst = dout; }

    int e0 = g_ptr[r];
    int e1 = (r == NN - 1) ? EE : g_ptr[r + 1];

    float4 acc = make_float4(0.f, 0.f, 0.f, 0.f);
    for (int e = e0; e < e1; ++e) {
        int   c = __ldg(&g_csr_col[e]);
        float w = __ldg(&g_csr_w[e]);
        float4 v = reinterpret_cast<const float4*>(src)[(size_t)c * G + g];
        acc.x += w * v.x; acc.y += w * v.y;
        acc.z += w * v.z; acc.w += w * v.w;
    }

    float4 d = reinterpret_cast<float4*>(dst)[(size_t)r * G + g];
    d.x += scale * acc.x; d.y += scale * acc.y;
    d.z += scale * acc.z; d.w += scale * acc.w;
    reinterpret_cast<float4*>(dst)[(size_t)r * G + g] = d;
}

// ---------------- launch ------------------------------------------------------
extern "C" void kernel_launch(void* const* d_in, const int* in_sizes, int n_in,
                              void* d_out, int out_size) {
    const float* x   = (const float*)d_in[0];
    const int*   ei  = (const int*)d_in[1];     // int32! (JAX x64 disabled downcasts int64)
    const float* W1  = (const float*)d_in[2];
    const float* b1  = (const float*)d_in[3];
    const float* W2  = (const float*)d_in[4];
    const float* b2  = (const float*)d_in[5];
    float*       out = (float*)d_out;

    const int* row = ei;
    const int* col = ei + EE;

    const int TB = 256;
    // --- CSR build + normalization ---
    k_init <<<(NN + TB - 1) / TB, TB>>>();
    k_deg  <<<(EE + TB - 1) / TB, TB>>>(row);
    k_scan1<<<NB, 1024>>>();
    k_scan2<<<1, 32>>>();
    k_scan3<<<(NN + TB - 1) / TB, TB>>>();
    k_dis  <<<(NN + TB - 1) / TB, TB>>>();
    k_fill <<<(EE + TB - 1) / TB, TB>>>(row, col);

    // --- Layer 1: H = x@(W0-W2)+b1, B = x@W1[1], C2 = x@W1[2] ---
    dim3 g1((NN + 63) / 64, 3);
    k_gemm1<<<g1, 256>>>(x, W1, b1);
    // B += 2*P(C2)   (P = -A_norm -> scale = -2)
    k_prop<16, 0><<<((unsigned)NN * 16 + TB - 1) / TB, TB>>>(out, -2.0f);
    // H += P(B)
    k_prop<16, 1><<<((unsigned)NN * 16 + TB - 1) / TB, TB>>>(out, -1.0f);

    // --- Layer 2 (relu on load): out = relu(H)@(W0'-W2')+b2, B2, C22 ---
    dim3 g2((NN + 63) / 64, 3);
    k_gemm2<<<g2, 128>>>(out, W2, b2);
    // B2 += 2*P(C22)
    k_prop<8, 2><<<((unsigned)NN * 8 + TB - 1) / TB, TB>>>(out, -2.0f);
    // out += P(B2)
    k_prop<8, 3><<<((unsigned)NN * 8 + TB - 1) / TB, TB>>>(out, -1.0f);
}

// round 7
// speedup vs baseline: 1.1342x; 1.1342x over previous
#include <cuda_runtime.h>

#define NN 100000
#define EE 1200000
#define NB 98            // ceil(NN / 1024)

// ---------------- scratch (device globals; no allocation allowed) ------------
__device__ __align__(16) int   g_degi[NN];
__device__ __align__(16) int   g_cnt [NN];
__device__ __align__(16) int   g_ptr [NN];        // CSR row start (exclusive scan)
__device__ __align__(16) int   g_bsum[NB];
__device__ __align__(16) float g_dis [NN];
__device__ __align__(16) int   g_csr_col[EE];
__device__ __align__(16) float g_csr_w  [EE];
__device__ __align__(16) float g_H  [(size_t)NN * 64];  // layer1: C0 (+b1), then += P(B)
__device__ __align__(16) float g_B  [(size_t)NN * 64];  // layer1: C1, then += 2P(C2)
__device__ __align__(16) float g_C2 [(size_t)NN * 64];  // layer1: x@W1[2]
__device__ __align__(16) float g_B2 [(size_t)NN * 32];  // layer2: C1', then += 2P(C2')
__device__ __align__(16) float g_C22[(size_t)NN * 32];  // layer2: relu(H)@W2[2]

// ---------------- f32x2 packed helpers ---------------------------------------
__device__ __forceinline__ unsigned long long pk2(float lo, float hi) {
    unsigned long long r;
    asm("mov.b64 %0, {%1, %2};" : "=l"(r) : "f"(lo), "f"(hi));
    return r;
}
__device__ __forceinline__ unsigned long long ffma2(unsigned long long a,
                                                    unsigned long long b,
                                                    unsigned long long c) {
    unsigned long long d;
    asm("fma.rn.f32x2 %0, %1, %2, %3;" : "=l"(d) : "l"(a), "l"(b), "l"(c));
    return d;
}
__device__ __forceinline__ void upk2(unsigned long long v, float& lo, float& hi) {
    asm("mov.b64 {%0, %1}, %2;" : "=f"(lo), "=f"(hi) : "l"(v));
}

// ---------------- degree / CSR build -----------------------------------------
__global__ void k_init() {
    int i = blockIdx.x * blockDim.x + threadIdx.x;
    if (i < NN) { g_degi[i] = 0; g_cnt[i] = 0; }
}

__global__ void k_deg(const int* __restrict__ row) {
    int e = blockIdx.x * blockDim.x + threadIdx.x;
    if (e < EE) {
        int r = row[e];
        if (r >= 0 && r < NN) atomicAdd(&g_degi[r], 1);
    }
}

__global__ __launch_bounds__(1024) void k_scan1() {
    __shared__ int s[1024];
    int i = blockIdx.x * 1024 + threadIdx.x;
    int v = (i < NN) ? g_degi[i] : 0;
    s[threadIdx.x] = v;
    __syncthreads();
    for (int off = 1; off < 1024; off <<= 1) {
        int a = (threadIdx.x >= off) ? s[threadIdx.x - off] : 0;
        __syncthreads();
        s[threadIdx.x] += a;
        __syncthreads();
    }
    if (i < NN) g_ptr[i] = s[threadIdx.x] - v;      // exclusive scan within block
    if (threadIdx.x == 1023) g_bsum[blockIdx.x] = s[1023];
}

// fixup: add prefix of block sums (computed per-block via shared reduction),
// and also compute deg^{-1/2} (fused, saves two kernels vs prior rounds)
__global__ __launch_bounds__(1024) void k_scan3() {
    __shared__ int s[128];
    const int b = blockIdx.x;
    const int t = threadIdx.x;
    if (t < 128) s[t] = (t < b) ? g_bsum[t] : 0;    // b <= NB-1 < 128
    __syncthreads();
    for (int o = 64; o > 0; o >>= 1) {
        if (t < o) s[t] += s[t + o];
        __syncthreads();
    }
    const int off = s[0];
    int i = b * 1024 + t;
    if (i < NN) {
        g_ptr[i] += off;
        int d = g_degi[i];
        g_dis[i] = (d > 0) ? rsqrtf((float)d) : 0.f;
    }
}

__global__ void k_fill(const int* __restrict__ row, const int* __restrict__ col) {
    int e = blockIdx.x * blockDim.x + threadIdx.x;
    if (e < EE) {
        int r = row[e];
        int c = col[e];
        if (r < 0 || r >= NN || c < 0 || c >= NN) return;
        int slot = g_ptr[r] + atomicAdd(&g_cnt[r], 1);
        g_csr_col[slot] = c;
        g_csr_w[slot]   = g_dis[r] * g_dis[c];
    }
}

// ---------------- fused GEMM, layer 1: x[N,64] -> {H, B, C2} in one kernel ---
// 64 nodes per block, 128 threads. Packed f32x2 over the node (row) axis:
// sX is [channel][node] so 8 consecutive nodes = 4 native f32x2 operands.
__global__ __launch_bounds__(128) void k_gemm1(const float* __restrict__ x,
                                               const float* __restrict__ W1,
                                               const float* __restrict__ b1) {
    __shared__ float sX[64][68];   // [channel][node], 68*4=272B row (16B aligned)
    __shared__ float sW[64][64];   // [channel][outcol]
    const int n0  = blockIdx.x * 64;
    const int tid = threadIdx.x;

    for (int i = tid; i < 1024; i += 128) {
        int n = i >> 4, c4 = i & 15;
        float4 v = make_float4(0.f, 0.f, 0.f, 0.f);
        if (n0 + n < NN)
            v = reinterpret_cast<const float4*>(x)[(size_t)(n0 + n) * 16 + c4];
        sX[c4 * 4 + 0][n] = v.x; sX[c4 * 4 + 1][n] = v.y;
        sX[c4 * 4 + 2][n] = v.z; sX[c4 * 4 + 3][n] = v.w;
    }

    const int tx = tid & 15;   // 16 col groups x4 = 64 cols
    const int ty = tid >> 4;   // 8 row groups  x8 = 64 nodes

    for (int which = 0; which < 3; ++which) {
        __syncthreads();   // prior compute done (and sX ready on first iter)
        for (int i = tid; i < 1024; i += 128) {
            int c = i >> 4, o4 = i & 15;
            float4 w = reinterpret_cast<const float4*>(W1 + which * 4096)[c * 16 + o4];
            if (which == 0) {
                float4 w2 = reinterpret_cast<const float4*>(W1 + 2 * 4096)[c * 16 + o4];
                w.x -= w2.x; w.y -= w2.y; w.z -= w2.z; w.w -= w2.w;
            }
            reinterpret_cast<float4*>(&sW[c][0])[o4] = w;
        }
        __syncthreads();

        unsigned long long acc2[4][4];   // [row-pair][col]
#pragma unroll
        for (int p = 0; p < 4; p++)
#pragma unroll
            for (int j = 0; j < 4; j++) acc2[p][j] = 0ull;

#pragma unroll 8
        for (int k = 0; k < 64; ++k) {
            const unsigned long long* ap =
                reinterpret_cast<const unsigned long long*>(&sX[k][ty * 8]);
            float4 w = *reinterpret_cast<const float4*>(&sW[k][tx * 4]);
            unsigned long long w2[4] = {pk2(w.x, w.x), pk2(w.y, w.y),
                                        pk2(w.z, w.z), pk2(w.w, w.w)};
#pragma unroll
            for (int p = 0; p < 4; p++) {
                unsigned long long a = ap[p];
#pragma unroll
                for (int j = 0; j < 4; j++) acc2[p][j] = ffma2(a, w2[j], acc2[p][j]);
            }
        }

        float4 bv = make_float4(0.f, 0.f, 0.f, 0.f);
        if (which == 0) bv = reinterpret_cast<const float4*>(b1)[tx];
        float* dst = (which == 0) ? g_H : (which == 1) ? g_B : g_C2;
#pragma unroll
        for (int p = 0; p < 4; p++) {
            float lo[4], hi[4];
#pragma unroll
            for (int j = 0; j < 4; j++) upk2(acc2[p][j], lo[j], hi[j]);
            int n = n0 + ty * 8 + p * 2;
            if (n < NN)
                reinterpret_cast<float4*>(dst)[(size_t)n * 16 + tx] =
                    make_float4(lo[0] + bv.x, lo[1] + bv.y, lo[2] + bv.z, lo[3] + bv.w);
            if (n + 1 < NN)
                reinterpret_cast<float4*>(dst)[(size_t)(n + 1) * 16 + tx] =
                    make_float4(hi[0] + bv.x, hi[1] + bv.y, hi[2] + bv.z, hi[3] + bv.w);
        }
    }
}

// ---------------- fused GEMM, layer 2: relu(H)[N,64] -> {out, B2, C22} -------
// 128 nodes per block, 128 threads (8 rows x 4 cols per thread, 32 cols).
__global__ __launch_bounds__(128) void k_gemm2(float* __restrict__ out,
                                               const float* __restrict__ W2,
                                               const float* __restrict__ b2) {
    __shared__ float sX[64][132];  // [channel][node], 132*4=528B (16B aligned)
    __shared__ float sW[64][32];
    const int n0  = blockIdx.x * 128;
    const int tid = threadIdx.x;

    for (int i = tid; i < 2048; i += 128) {
        int n = i >> 4, c4 = i & 15;
        float4 v = make_float4(0.f, 0.f, 0.f, 0.f);
        if (n0 + n < NN) {
            v = reinterpret_cast<const float4*>(g_H)[(size_t)(n0 + n) * 16 + c4];
            v.x = fmaxf(v.x, 0.f); v.y = fmaxf(v.y, 0.f);
            v.z = fmaxf(v.z, 0.f); v.w = fmaxf(v.w, 0.f);
        }
        sX[c4 * 4 + 0][n] = v.x; sX[c4 * 4 + 1][n] = v.y;
        sX[c4 * 4 + 2][n] = v.z; sX[c4 * 4 + 3][n] = v.w;
    }

    const int tx = tid & 7;    // 8 col groups x4 = 32 cols
    const int ty = tid >> 3;   // 16 row groups x8 = 128 nodes

    for (int which = 0; which < 3; ++which) {
        __syncthreads();
        for (int i = tid; i < 512; i += 128) {
            int c = i >> 3, o4 = i & 7;
            float4 w = reinterpret_cast<const float4*>(W2 + which * 2048)[c * 8 + o4];
            if (which == 0) {
                float4 w2 = reinterpret_cast<const float4*>(W2 + 2 * 2048)[c * 8 + o4];
                w.x -= w2.x; w.y -= w2.y; w.z -= w2.z; w.w -= w2.w;
            }
            reinterpret_cast<float4*>(&sW[c][0])[o4] = w;
        }
        __syncthreads();

        unsigned long long acc2[4][4];
#pragma unroll
        for (int p = 0; p < 4; p++)
#pragma unroll
            for (int j = 0; j < 4; j++) acc2[p][j] = 0ull;

#pragma unroll 8
        for (int k = 0; k < 64; ++k) {
            const unsigned long long* ap =
                reinterpret_cast<const unsigned long long*>(&sX[k][ty * 8]);
            float4 w = *reinterpret_cast<const float4*>(&sW[k][tx * 4]);
            unsigned long long w2[4] = {pk2(w.x, w.x), pk2(w.y, w.y),
                                        pk2(w.z, w.z), pk2(w.w, w.w)};
#pragma unroll
            for (int p = 0; p < 4; p++) {
                unsigned long long a = ap[p];
#pragma unroll
                for (int j = 0; j < 4; j++) acc2[p][j] = ffma2(a, w2[j], acc2[p][j]);
            }
        }

        float4 bv = make_float4(0.f, 0.f, 0.f, 0.f);
        if (which == 0) bv = reinterpret_cast<const float4*>(b2)[tx];
        float* dst = (which == 0) ? out : (which == 1) ? g_B2 : g_C22;
#pragma unroll
        for (int p = 0; p < 4; p++) {
            float lo[4], hi[4];
#pragma unroll
            for (int j = 0; j < 4; j++) upk2(acc2[p][j], lo[j], hi[j]);
            int n = n0 + ty * 8 + p * 2;
            if (n < NN)
                reinterpret_cast<float4*>(dst)[(size_t)n * 8 + tx] =
                    make_float4(lo[0] + bv.x, lo[1] + bv.y, lo[2] + bv.z, lo[3] + bv.w);
            if (n + 1 < NN)
                reinterpret_cast<float4*>(dst)[(size_t)(n + 1) * 8 + tx] =
                    make_float4(hi[0] + bv.x, hi[1] + bv.y, hi[2] + bv.z, hi[3] + bv.w);
        }
    }
}

// ---------------- pull-style propagation: dst[r] += scale * sum_e w*src[col] -
// G = channels/4 (16 for 64ch, 8 for 32ch). One G-thread group per row.
// No atomics; unroll-by-2 with dual accumulators to double MLP.
template <int G, int MODE>
__global__ __launch_bounds__(256) void k_prop(float* __restrict__ dout, float scale) {
    unsigned t = blockIdx.x * 256u + threadIdx.x;
    unsigned r = t / G;
    unsigned g = t & (G - 1);
    if (r >= NN) return;

    const float* src;
    float* dst;
    if (MODE == 0)      { src = g_C2;  dst = g_B;  }
    else if (MODE == 1) { src = g_B;   dst = g_H;  }
    else if (MODE == 2) { src = g_C22; dst = g_B2; }
    else                { src = g_B2;  dst = dout; }

    int e  = g_ptr[r];
    int e1 = (r == NN - 1) ? EE : g_ptr[r + 1];

    float4 a0 = make_float4(0.f, 0.f, 0.f, 0.f);
    float4 a1 = make_float4(0.f, 0.f, 0.f, 0.f);
    for (; e + 1 < e1; e += 2) {
        int   c0 = __ldg(&g_csr_col[e]);
        int   c1 = __ldg(&g_csr_col[e + 1]);
        float w0 = __ldg(&g_csr_w[e]);
        float w1 = __ldg(&g_csr_w[e + 1]);
        float4 v0 = reinterpret_cast<const float4*>(src)[(size_t)c0 * G + g];
        float4 v1 = reinterpret_cast<const float4*>(src)[(size_t)c1 * G + g];
        a0.x += w0 * v0.x; a0.y += w0 * v0.y; a0.z += w0 * v0.z; a0.w += w0 * v0.w;
        a1.x += w1 * v1.x; a1.y += w1 * v1.y; a1.z += w1 * v1.z; a1.w += w1 * v1.w;
    }
    if (e < e1) {
        int   c0 = __ldg(&g_csr_col[e]);
        float w0 = __ldg(&g_csr_w[e]);
        float4 v0 = reinterpret_cast<const float4*>(src)[(size_t)c0 * G + g];
        a0.x += w0 * v0.x; a0.y += w0 * v0.y; a0.z += w0 * v0.z; a0.w += w0 * v0.w;
    }
    a0.x += a1.x; a0.y += a1.y; a0.z += a1.z; a0.w += a1.w;

    float4 d = reinterpret_cast<float4*>(dst)[(size_t)r * G + g];
    d.x += scale * a0.x; d.y += scale * a0.y;
    d.z += scale * a0.z; d.w += scale * a0.w;
    reinterpret_cast<float4*>(dst)[(size_t)r * G + g] = d;
}

// ---------------- launch ------------------------------------------------------
extern "C" void kernel_launch(void* const* d_in, const int* in_sizes, int n_in,
                              void* d_out, int out_size) {
    const float* x   = (const float*)d_in[0];
    const int*   ei  = (const int*)d_in[1];     // int32 (JAX x64 disabled)
    const float* W1  = (const float*)d_in[2];
    const float* b1  = (const float*)d_in[3];
    const float* W2  = (const float*)d_in[4];
    const float* b2  = (const float*)d_in[5];
    float*       out = (float*)d_out;

    const int* row = ei;
    const int* col = ei + EE;

    const int TB = 256;
    // --- CSR build + normalization ---
    k_init <<<(NN + TB - 1) / TB, TB>>>();
    k_deg  <<<(EE + TB - 1) / TB, TB>>>(row);
    k_scan1<<<NB, 1024>>>();
    k_scan3<<<NB, 1024>>>();          // fixup + deg^{-1/2}, no serial kernel
    k_fill <<<(EE + TB - 1) / TB, TB>>>(row, col);

    // --- Layer 1: H = x@(W0-W2)+b1, B = x@W1[1], C2 = x@W1[2] (one kernel) ---
    k_gemm1<<<(NN + 63) / 64, 128>>>(x, W1, b1);
    // B += 2*P(C2)   (P = -A_norm -> scale = -2)
    k_prop<16, 0><<<((unsigned)NN * 16 + TB - 1) / TB, TB>>>(out, -2.0f);
    // H += P(B)
    k_prop<16, 1><<<((unsigned)NN * 16 + TB - 1) / TB, TB>>>(out, -1.0f);

    // --- Layer 2 (relu on load): out = relu(H)@(W0'-W2')+b2, B2, C22 ---
    k_gemm2<<<(NN + 127) / 128, 128>>>(out, W2, b2);
    // B2 += 2*P(C22)
    k_prop<8, 2><<<((unsigned)NN * 8 + TB - 1) / TB, TB>>>(out, -2.0f);
    // out += P(B2)
    k_prop<8, 3><<<((unsigned)NN * 8 + TB - 1) / TB, TB>>>(out, -1.0f);
}